// round 3
// baseline (speedup 1.0000x reference)
#include <cuda_runtime.h>
#include <cstdint>

#define B_  8
#define C_  32
#define H_  64
#define W_  64
#define F_  64
#define TH  32            // rows of output per CTA
#define NT  256           // threads per CTA

typedef unsigned long long ull;

// ---- f32x2 packed helpers (sm_100+ packed fp32 pipe) ----
__device__ __forceinline__ ull pk2(float lo, float hi) {
    ull r; asm("mov.b64 %0, {%1, %2};" : "=l"(r) : "f"(lo), "f"(hi)); return r;
}
__device__ __forceinline__ void upk2(ull v, float& lo, float& hi) {
    asm("mov.b64 {%0, %1}, %2;" : "=f"(lo), "=f"(hi) : "l"(v));
}
__device__ __forceinline__ ull ffma2(ull a, ull b, ull c) {
    ull d; asm("fma.rn.f32x2 %0, %1, %2, %3;" : "=l"(d) : "l"(a), "l"(b), "l"(c)); return d;
}
__device__ __forceinline__ ull fmul2(ull a, ull b) {
    ull d; asm("mul.rn.f32x2 %0, %1, %2;" : "=l"(d) : "l"(a), "l"(b)); return d;
}
__device__ __forceinline__ float frcp(float x) {
    float r; asm("rcp.approx.ftz.f32 %0, %1;" : "=f"(r) : "f"(x)); return r;
}

// One CTA = one (b, f, 32-row tile). Coefs for filter f staged in smem as
// duplicated f32x2 (LDS.64 broadcast, uniform across CTA). x tile (one channel,
// zero-padded halo) staged in smem per channel iteration.
__global__ __launch_bounds__(NT, 2)
void kan_kernel(const float* __restrict__ x,
                const float* __restrict__ numc,
                const float* __restrict__ denc,
                float* __restrict__ out)
{
    // coef_s[(tap*32 + c)*10 + j]: j=0..5 num a0..a5, j=6..9 den b1..b4 (dup'd)
    __shared__ ull   coef_s[9 * C_ * 10];        // 23040 B
    __shared__ float xs[(TH + 2) * 68];          //  9248 B (66 cols + pad)

    const int tile = blockIdx.x;                 // 0..H/TH-1
    const int f    = blockIdx.y;
    const int b    = blockIdx.z;
    const int h0   = tile * TH;
    const int tid  = threadIdx.x;

    // ---- stage filter-f coefficients, duplicated into f32x2 lanes ----
    {
        const float* np = numc + (size_t)f * 9 * C_ * 6;
        for (int i = tid; i < 9 * C_ * 6; i += NT) {
            int t = i / (C_ * 6);
            int r = i - t * (C_ * 6);
            int c = r / 6, j = r - c * 6;
            float v = np[i];
            coef_s[(t * C_ + c) * 10 + j] = pk2(v, v);
        }
        const float* dp = denc + (size_t)f * 9 * C_ * 4;
        for (int i = tid; i < 9 * C_ * 4; i += NT) {
            int t = i / (C_ * 4);
            int r = i - t * (C_ * 4);
            int c = r / 4, j = r - c * 4;
            float v = dp[i];
            coef_s[(t * C_ + c) * 10 + 6 + j] = pk2(v, v);
        }
    }

    // thread -> (base row r0 in 0..3, col w); 8 pixels per thread at rows r0+4k
    const int r0 = tid >> 6;
    const int w  = tid & 63;

    float acc[8];
    #pragma unroll
    for (int k = 0; k < 8; k++) acc[k] = 0.f;

    for (int c = 0; c < C_; c++) {
        __syncthreads();   // protect xs from previous iteration's readers
        // stage x[b, c, h0-1 .. h0+TH, -1 .. 64] with zero halo
        const float* xc = x + (((size_t)b * C_ + c) * H_) * W_;
        for (int i = tid; i < (TH + 2) * 66; i += NT) {
            int rr = i / 66, cc = i - rr * 66;
            int gh = h0 + rr - 1, gw = cc - 1;
            float v = 0.f;
            if (gh >= 0 && gh < H_ && gw >= 0 && gw < W_)
                v = xc[gh * W_ + gw];
            xs[rr * 68 + cc] = v;
        }
        __syncthreads();

        #pragma unroll
        for (int tap = 0; tap < 9; tap++) {
            const int ta = tap / 3, tb = tap - ta * 3;
            const ull* cs = &coef_s[(tap * C_ + c) * 10];
            const ull a0 = cs[0], a1 = cs[1], a2 = cs[2],
                      a3 = cs[3], a4 = cs[4], a5 = cs[5];
            const ull b1 = cs[6], b2 = cs[7], b3 = cs[8], b4 = cs[9];

            #pragma unroll
            for (int m = 0; m < 4; m++) {
                // pair m = pixels at rows (r0+8m) and (r0+8m+4), col w
                const int rbase = r0 + 8 * m + ta;        // smem row (halo-shifted)
                const int col   = w + tb;                  // smem col (halo-shifted)
                float x0 = xs[rbase * 68 + col];
                float x1 = xs[(rbase + 4) * 68 + col];
                ull xp = pk2(x0, x1);

                // numerator Horner: a0 + x(a1 + x(a2 + x(a3 + x(a4 + x a5))))
                ull num = ffma2(a5, xp, a4);
                num = ffma2(num, xp, a3);
                num = ffma2(num, xp, a2);
                num = ffma2(num, xp, a1);
                num = ffma2(num, xp, a0);
                // q = b1 + x(b2 + x(b3 + x b4));  den = 1 + |q*x|
                ull q = ffma2(b4, xp, b3);
                q = ffma2(q, xp, b2);
                q = ffma2(q, xp, b1);
                ull t = fmul2(q, xp);

                float t0, t1; upk2(t, t0, t1);
                float d0 = 1.0f + fabsf(t0);               // FADD with free |.|
                float d1 = 1.0f + fabsf(t1);
                float i0 = frcp(d0), i1 = frcp(d1);        // MUFU.RCP
                float n0, n1; upk2(num, n0, n1);
                acc[2 * m]     = fmaf(n0, i0, acc[2 * m]);
                acc[2 * m + 1] = fmaf(n1, i1, acc[2 * m + 1]);
            }
        }
    }

    // ---- write out[b][f][h][w] ----
    float* ob = out + (((size_t)b * F_ + f) * H_ + h0) * W_;
    #pragma unroll
    for (int k = 0; k < 8; k++)
        ob[(r0 + 4 * k) * W_ + w] = acc[k];
}

extern "C" void kernel_launch(void* const* d_in, const int* in_sizes, int n_in,
                              void* d_out, int out_size)
{
    const float* x  = (const float*)d_in[0];
    const float* nc = (const float*)d_in[1];
    const float* dc = (const float*)d_in[2];
    float* out = (float*)d_out;

    dim3 grid(H_ / TH, F_, B_);   // 2 x 64 x 8 = 1024 CTAs
    kan_kernel<<<grid, NT>>>(x, nc, dc, out);
}

// round 5
// speedup vs baseline: 1.1242x; 1.1242x over previous
#include <cuda_runtime.h>
#include <cstdint>

#define B_  8
#define C_  32
#define H_  64
#define W_  64
#define F_  64
#define TH  32               // output rows per CTA
#define NT  256
#define XROWS (TH + 2)       // 34 staged rows (halo)
#define XSTR  68             // padded smem row stride (floats)
#define XS_ELE (XROWS * XSTR)

typedef unsigned long long ull;

// ---- packed f32x2 helpers (sm_10x packed fp32 pipe, PTX-only) ----
__device__ __forceinline__ ull pk2(float lo, float hi) {
    ull r; asm("mov.b64 %0, {%1, %2};" : "=l"(r) : "f"(lo), "f"(hi)); return r;
}
__device__ __forceinline__ void upk2(ull v, float& lo, float& hi) {
    asm("mov.b64 {%0, %1}, %2;" : "=f"(lo), "=f"(hi) : "l"(v));
}
__device__ __forceinline__ ull ffma2(ull a, ull b, ull c) {
    ull d; asm("fma.rn.f32x2 %0, %1, %2, %3;" : "=l"(d) : "l"(a), "l"(b), "l"(c)); return d;
}
__device__ __forceinline__ ull fmul2(ull a, ull b) {
    ull d; asm("mul.rn.f32x2 %0, %1, %2;" : "=l"(d) : "l"(a), "l"(b)); return d;
}
__device__ __forceinline__ ull fadd2(ull a, ull b) {
    ull d; asm("add.rn.f32x2 %0, %1, %2;" : "=l"(d) : "l"(a), "l"(b)); return d;
}
__device__ __forceinline__ ull and64(ull a, ull b) {
    ull d; asm("and.b64 %0, %1, %2;" : "=l"(d) : "l"(a), "l"(b)); return d;
}
__device__ __forceinline__ float frcp(float x) {
    float r; asm("rcp.approx.ftz.f32 %0, %1;" : "=f"(r) : "f"(x)); return r;
}
__device__ __forceinline__ uint32_t s2u32(const void* p) {
    uint32_t a;
    asm("{ .reg .u64 t; cvta.to.shared.u64 t, %1; cvt.u32.u64 %0, t; }"
        : "=r"(a) : "l"(p));
    return a;
}
// cp.async 4B with zfill via src-size (0 => zero-fill destination)
__device__ __forceinline__ void cpa4(uint32_t dst, const float* src, int ssz) {
    asm volatile("cp.async.ca.shared.global [%0], [%1], 4, %2;"
                 :: "r"(dst), "l"(src), "r"(ssz) : "memory");
}
__device__ __forceinline__ void cpa_commit() {
    asm volatile("cp.async.commit_group;" ::: "memory");
}
template <int N>
__device__ __forceinline__ void cpa_wait() {
    asm volatile("cp.async.wait_group %0;" :: "n"(N) : "memory");
}

// Stage one halo'd channel tile x[b,c, h0-1 .. h0+TH, -1..64] into smem buffer.
// Warp-row mapping: warp `wid` takes rows wid+8t; lane covers cols lane, lane+32,
// (+64 for lanes 0,1). Out-of-range elements zero-filled via src-size=0.
__device__ __forceinline__ void stage_tile(const float* __restrict__ xc, int h0,
                                           uint32_t dstbase, int wid, int lane)
{
    #pragma unroll
    for (int t = 0; t < 5; ++t) {
        int rr = wid + 8 * t;
        if (t < 4 || wid < 2) {            // rr < 34
            int gh = h0 - 1 + rr;
            bool ghv = (gh >= 0) && (gh < H_);
            const float* rowp = xc + (ghv ? gh : 0) * W_;
            uint32_t drow = dstbase + (uint32_t)(rr * XSTR) * 4u;

            // cc = lane
            {
                int gw = lane - 1;
                bool v = ghv && (gw >= 0);
                cpa4(drow + lane * 4u, rowp + (v ? gw : 0), v ? 4 : 0);
            }
            // cc = lane + 32
            {
                int gw = lane + 31;
                cpa4(drow + (lane + 32) * 4u, rowp + (ghv ? gw : 0), ghv ? 4 : 0);
            }
            // cc = lane + 64 (lanes 0,1 only): gw = 63 valid, gw = 64 invalid
            if (lane < 2) {
                int gw = lane + 63;
                bool v = ghv && (gw < W_);
                cpa4(drow + (lane + 64) * 4u, rowp + (v ? gw : 0), v ? 4 : 0);
            }
        }
    }
}

__global__ __launch_bounds__(NT, 3)
void kan_kernel(const float* __restrict__ x,
                const float* __restrict__ numc,
                const float* __restrict__ denc,
                float* __restrict__ out)
{
    // coef_s[(tap*32 + c)*10 + j]: j=0..5 num a0..a5, j=6..9 den b1..b4,
    // each duplicated into both f32x2 lanes. Entry = 80B => 16B-aligned.
    __shared__ __align__(16) ull coef_s[9 * C_ * 10];   // 23040 B
    __shared__ float xs[2][XS_ELE];                      // 18496 B (ping-pong)

    const int tile = blockIdx.x;
    const int f    = blockIdx.y;
    const int b    = blockIdx.z;
    const int h0   = tile * TH;
    const int tid  = threadIdx.x;
    const int wid  = tid >> 5, lane = tid & 31;

    const float* xb_gl = x + (((size_t)b * C_) * H_) * W_;   // channel 0 base
    const uint32_t xs0 = s2u32(&xs[0][0]);
    const uint32_t xs1 = s2u32(&xs[1][0]);

    // ---- prefetch channel 0 ----
    stage_tile(xb_gl, h0, xs0, wid, lane);
    cpa_commit();

    // ---- stage filter-f coefficients (duplicated f32x2) ----
    {
        const float* np = numc + (size_t)f * 9 * C_ * 6;
        for (int i = tid; i < 9 * C_ * 6; i += NT) {
            int t = i / (C_ * 6);
            int r = i - t * (C_ * 6);
            int c = r / 6, j = r - c * 6;
            float v = np[i];
            coef_s[(t * C_ + c) * 10 + j] = pk2(v, v);
        }
        const float* dp = denc + (size_t)f * 9 * C_ * 4;
        for (int i = tid; i < 9 * C_ * 4; i += NT) {
            int t = i / (C_ * 4);
            int r = i - t * (C_ * 4);
            int c = r / 4, j = r - c * 4;
            float v = dp[i];
            coef_s[(t * C_ + c) * 10 + 6 + j] = pk2(v, v);
        }
    }

    const int r0 = tid >> 6;        // 0..3
    const int w  = tid & 63;

    const ull ABS2 = 0x7FFFFFFF7FFFFFFFULL;
    const ull ONE2 = pk2(1.0f, 1.0f);

    ull accp[4];
    #pragma unroll
    for (int m = 0; m < 4; m++) accp[m] = pk2(0.f, 0.f);

    #pragma unroll 1
    for (int c = 0; c < C_; ++c) {
        // prefetch next channel into the other buffer (overlaps this compute)
        if (c + 1 < C_) {
            const float* xc1 = xb_gl + (size_t)(c + 1) * H_ * W_;
            stage_tile(xc1, h0, ((c + 1) & 1) ? xs1 : xs0, wid, lane);
            cpa_commit();
            cpa_wait<1>();          // buffer for channel c is complete
        } else {
            cpa_wait<0>();
        }
        __syncthreads();            // all threads' copies visible

        const float* xb = xs[c & 1];
        const float* xrow = xb + r0 * XSTR + w;   // immediate offsets below

        #pragma unroll
        for (int tap = 0; tap < 9; tap++) {
            const int ta = tap / 3, tb = tap - ta * 3;
            const ulonglong2* cs2 =
                reinterpret_cast<const ulonglong2*>(&coef_s[(tap * C_ + c) * 10]);
            const ulonglong2 v0 = cs2[0], v1 = cs2[1], v2 = cs2[2],
                             v3 = cs2[3], v4 = cs2[4];
            const ull a0 = v0.x, a1 = v0.y, a2 = v1.x, a3 = v1.y,
                      a4 = v2.x, a5 = v2.y;
            const ull b1 = v3.x, b2 = v3.y, b3 = v4.x, b4 = v4.y;

            #pragma unroll
            for (int m = 0; m < 4; m++) {
                // pixels at rows (r0+8m) and (r0+8m+4), col w
                float x0 = xrow[(8 * m + ta) * XSTR + tb];
                float x1 = xrow[(8 * m + 4 + ta) * XSTR + tb];
                ull xp = pk2(x0, x1);

                // numerator Horner a0..a5
                ull num = ffma2(a5, xp, a4);
                num = ffma2(num, xp, a3);
                num = ffma2(num, xp, a2);
                num = ffma2(num, xp, a1);
                num = ffma2(num, xp, a0);
                // q = b1 + x(b2 + x(b3 + x b4)); den = 1 + |q*x|
                ull q = ffma2(b4, xp, b3);
                q = ffma2(q, xp, b2);
                q = ffma2(q, xp, b1);
                ull t = and64(fmul2(q, xp), ABS2);
                ull den = fadd2(ONE2, t);

                float d0, d1; upk2(den, d0, d1);
                ull inv = pk2(frcp(d0), frcp(d1));
                accp[m] = ffma2(num, inv, accp[m]);
            }
        }
        if (c + 1 < C_) __syncthreads();   // readers done before next overwrite
    }

    // ---- write out[b][f][h][w]; accp[m] = rows (r0+8m, r0+8m+4) ----
    float* ob = out + (((size_t)b * F_ + f) * H_ + h0) * W_;
    #pragma unroll
    for (int m = 0; m < 4; m++) {
        float lo, hi; upk2(accp[m], lo, hi);
        ob[(r0 + 8 * m) * W_ + w]     = lo;
        ob[(r0 + 8 * m + 4) * W_ + w] = hi;
    }
}

extern "C" void kernel_launch(void* const* d_in, const int* in_sizes, int n_in,
                              void* d_out, int out_size)
{
    const float* x  = (const float*)d_in[0];
    const float* nc = (const float*)d_in[1];
    const float* dc = (const float*)d_in[2];
    float* out = (float*)d_out;

    dim3 grid(H_ / TH, F_, B_);   // 2 x 64 x 8 = 1024 CTAs
    kan_kernel<<<grid, NT>>>(x, nc, dc, out);
}